// round 9
// baseline (speedup 1.0000x reference)
#include <cuda_runtime.h>

// Random_RNN two-hop sparse propagation — ONE fused persistent kernel,
// line-padded atomic counters (the R8 fix that took build 22.4->8.5us).
//
// Hop1: acc1[j][b] = sum_{in-edges dst=j} w * x[b][src]
// Hop2: out[b][o]  = sum_{ass-edges dst=OUT0+o} w * acc1[src][b]
// Only ass-edges landing on OUTPUT nodes matter (~52K of ~891K) -> filter.
//
// Evidence: ~8-10us of the 25.5us total is multi-launch overhead (3 launches).
// Fusing phases behind device-wide sense-reversing barriers removes 2 launch
// gaps while keeping the full 303K-thread build width (592 blocks x 512,
// launch_bounds(512,4) -> <=32 regs -> 4 CTAs/SM -> whole grid resident, so
// the spin barrier cannot deadlock). Sense flips exactly twice per launch and
// counters are consumed-and-reset -> graph replays see identical state.

#define B      128
#define IN_F   256
#define N_ASS  4096
#define OUT_F  256
#define ASS0   256
#define OUT0   (IN_F + N_ASS)   // 4352
#define CAP1   40               // assoc in-degree: E 12.8, sd 3.5 (max ~26)
#define CAP2   288              // output in-degree: E 204.8, sd 14 (max ~252)
#define XT_N   (IN_F * B)       // 32768
#define CSTR   32               // counter stride: 32 ints = 128B = 1 L2 line
#define NBLK   592
#define NTHR   512

__device__ float2       g_b1[N_ASS * CAP1];  // {src*B (int bits), w}
__device__ float2       g_b2[OUT_F * CAP2];
__device__ int          g_c1[N_ASS * CSTR];  // one counter per L2 line
__device__ int          g_c2[OUT_F * CSTR];
__device__ float        g_xT[IN_F * B];      // x transposed [src][b]
__device__ float        g_acc1[N_ASS * B];   // assoc activations (L2-resident)
__device__ int          g_count;             // barrier arrivals (returns to 0)
__device__ volatile int g_sense;             // flips 2x/launch -> replay-stable

__device__ __forceinline__ void grid_barrier(int* local_sense) {
    __syncthreads();
    if (threadIdx.x == 0) {
        int s = *local_sense ^ 1;
        __threadfence();                               // publish block's writes
        if (atomicAdd(&g_count, 1) == NBLK - 1) {
            g_count = 0;
            __threadfence();
            g_sense = s;                               // release
        } else {
            while (g_sense != s) {}
        }
        *local_sense = s;
    }
    __syncthreads();
    __threadfence();                                   // acquire peers' writes
}

__global__ void __launch_bounds__(NTHR, 4)
k_fused(const float* __restrict__ x,
        const int* __restrict__ in_src, const int* __restrict__ in_dst,
        const float* __restrict__ in_w, int E_in,
        const int* __restrict__ a_src, const int* __restrict__ a_dst,
        const float* __restrict__ a_w, int E_ass,
        float* __restrict__ out) {
    const int tid = threadIdx.x;
    const int i   = blockIdx.x * NTHR + tid;
    const int nt  = NBLK * NTHR;                       // 303104
    int local_sense = 0;

    // ================= Phase A: transpose + bucket build (== R8 build) ======
    for (int idx = i; idx < XT_N; idx += nt) {         // x [B][IN_F]->xT[IN_F][B]
        int b = idx >> 8, s = idx & 255;
        g_xT[s * B + b] = x[idx];
    }
    for (int e = i; e < E_in; e += nt) {               // hop1 edges (~52K)
        int   d = in_dst[e] - ASS0;
        int   s = in_src[e];
        float w = in_w[e];
        int pos = atomicAdd(&g_c1[d * CSTR], 1);
        g_b1[d * CAP1 + pos] = make_float2(__int_as_float(s * B), w);
    }
    {                                                  // hop2 scan (~891K)
        const int  E4 = E_ass >> 2;
        const int4* a4 = (const int4*)a_dst;
        for (int q = i; q < E4; q += nt) {
            int4 d4 = __ldg(&a4[q]);
            int  e0 = q << 2;
            int dd[4] = {d4.x, d4.y, d4.z, d4.w};
#pragma unroll
            for (int m = 0; m < 4; m++) {
                if (dd[m] >= OUT0) {
                    int   d = dd[m] - OUT0;
                    int   s = __ldg(&a_src[e0 + m]) - ASS0;
                    float w = __ldg(&a_w[e0 + m]);
                    int pos = atomicAdd(&g_c2[d * CSTR], 1);
                    g_b2[d * CAP2 + pos] = make_float2(__int_as_float(s * B), w);
                }
            }
        }
        for (int e = (E4 << 2) + i; e < E_ass; e += nt) {  // tail
            int d = a_dst[e];
            if (d >= OUT0) {
                int   dd = d - OUT0;
                int   s  = a_src[e] - ASS0;
                float w  = a_w[e];
                int pos  = atomicAdd(&g_c2[dd * CSTR], 1);
                g_b2[dd * CAP2 + pos] = make_float2(__int_as_float(s * B), w);
            }
        }
    }

    grid_barrier(&local_sense);

    // ================= Phase B: hop1 gather =================
    // 4 nodes per block-iteration (128 threads each); 1024 groups / 592 blocks.
    {
        __shared__ int sn[4];
        int g = tid >> 7, b = tid & 127;
        for (int it = blockIdx.x; it < N_ASS / 4; it += NBLK) {
            int j = (it << 2) + g;
            if (b == 0) { sn[g] = g_c1[j * CSTR]; g_c1[j * CSTR] = 0; }
            __syncthreads();
            int n = sn[g];
            const float2* bk = &g_b1[j * CAP1];
            float r = 0.f;
            for (int e = 0; e < n; e += 4) {           // 4-wide predicated rounds
                float2 p[4];
#pragma unroll
                for (int k = 0; k < 4; k++)
                    p[k] = (e + k < n) ? __ldg(&bk[e + k]) : make_float2(0.f, 0.f);
#pragma unroll
                for (int k = 0; k < 4; k++)
                    r += p[k].y * g_xT[__float_as_int(p[k].x) + b];
            }
            g_acc1[j * B + b] = r;
            __syncthreads();                           // sn reused next iter
        }
    }

    grid_barrier(&local_sense);

    // ================= Phase C: hop2 gather =================
    // One output per block (first 256 blocks); 4 edge-groups x 128 threads,
    // ~51 edges/group, 4-wide predicated rounds, smem reduce.
    if (blockIdx.x < OUT_F) {
        __shared__ int   sc;
        __shared__ float part[3][B];
        int o = blockIdx.x;
        int g = tid >> 7, b = tid & 127;
        if (tid == 0) { sc = g_c2[o * CSTR]; g_c2[o * CSTR] = 0; }
        __syncthreads();
        int n  = sc;
        int e0 = (n * g)       >> 2;
        int e1 = (n * (g + 1)) >> 2;
        const float2* bk = &g_b2[o * CAP2];
        float r = 0.f;
        for (int e = e0; e < e1; e += 4) {
            float2 p[4];
#pragma unroll
            for (int k = 0; k < 4; k++)
                p[k] = (e + k < e1) ? __ldg(&bk[e + k]) : make_float2(0.f, 0.f);
#pragma unroll
            for (int k = 0; k < 4; k++)
                r += p[k].y * g_acc1[__float_as_int(p[k].x) + b];
        }
        if (g > 0) part[g - 1][b] = r;
        __syncthreads();
        if (g == 0)
            out[b * OUT_F + o] = r + part[0][b] + part[1][b] + part[2][b];
    }
}

// ---------------------------------------------------------------- launch
extern "C" void kernel_launch(void* const* d_in, const int* in_sizes, int n_in,
                              void* d_out, int out_size) {
    const float* x      = (const float*)d_in[0];
    const float* in_w   = (const float*)d_in[1];
    const float* a_w    = (const float*)d_in[2];
    const int*   in_src = (const int*)d_in[3];
    const int*   in_dst = (const int*)d_in[4];
    const int*   a_src  = (const int*)d_in[5];
    const int*   a_dst  = (const int*)d_in[6];
    int E_in  = in_sizes[1];
    int E_ass = in_sizes[2];
    float* out = (float*)d_out;

    k_fused<<<NBLK, NTHR>>>(x, in_src, in_dst, in_w, E_in,
                            a_src, a_dst, a_w, E_ass, out);
}

// round 10
// speedup vs baseline: 1.1550x; 1.1550x over previous
#include <cuda_runtime.h>

// Random_RNN two-hop sparse propagation — 3-kernel bucket pipeline (best: R8),
// with vectorized hit-loads in the build scan.
//
// Hop1: acc1[j][b] = sum_{in-edges dst=j} w * x[b][src]
// Hop2: out[b][o]  = sum_{ass-edges dst=OUT0+o} w * acc1[src][b]
// Only ass-edges landing on OUTPUT nodes matter (~52K of ~891K) -> filter.
//
// Established: (1) counters MUST be one-per-128B-line (L2 atomic units
// serialize per line; this was 14us of hidden cost through R7). (2) Fusion
// behind grid barriers loses ~20us to barrier/phase skew — 3 launches win.
// Counters are consumed-and-reset by the hop kernels so every launch/replay
// sees identical initial state.

#define B      128
#define IN_F   256
#define N_ASS  4096
#define OUT_F  256
#define ASS0   256
#define OUT0   (IN_F + N_ASS)   // 4352
#define CAP1   40               // assoc in-degree: E 12.8, sd 3.5 (max ~26)
#define CAP2   288              // output in-degree: E 204.8, sd 14 (max ~252)
#define XT_N   (IN_F * B)       // 32768
#define CSTR   32               // counter stride: 32 ints = 128B = 1 L2 line

__device__ float2 g_b1[N_ASS * CAP1];   // {src*B (int bits), w}  1.3 MB
__device__ float2 g_b2[OUT_F * CAP2];   //                        0.6 MB
__device__ int    g_c1[N_ASS * CSTR];   // one counter per L2 line
__device__ int    g_c2[OUT_F * CSTR];
__device__ float  g_xT[IN_F * B];       // x transposed [src][b] (L1-resident)
__device__ float  g_acc1[N_ASS * B];    // assoc activations (2 MB, L2-resident)

// ---------------------------------------------------------------- build
// Grid-stride, 1184 blocks x 256 (8 CTA/SM, one wave).
// Hot path: int4 dst scan; on any hit in a group (~22% of groups), pull the
// matching int4 of src and float4 of w in one shot (vs 2 scalar scattered
// loads per hit edge).
__global__ void __launch_bounds__(256, 8)
k_build(const float* __restrict__ x,
        const int* __restrict__ in_src, const int* __restrict__ in_dst,
        const float* __restrict__ in_w, int E_in,
        const int* __restrict__ a_src, const int* __restrict__ a_dst,
        const float* __restrict__ a_w, int E_ass) {
    const int i  = blockIdx.x * 256 + threadIdx.x;
    const int nt = gridDim.x * 256;

    // x [B][IN_F] -> xT [IN_F][B]
    for (int idx = i; idx < XT_N; idx += nt) {
        int b = idx >> 8, s = idx & 255;               // IN_F == 256
        g_xT[s * B + b] = x[idx];
    }

    // hop1 edges (~52K)
    for (int e = i; e < E_in; e += nt) {
        int   d = in_dst[e] - ASS0;
        int   s = in_src[e];
        float w = in_w[e];
        int pos = atomicAdd(&g_c1[d * CSTR], 1);       // line-private counter
        g_b1[d * CAP1 + pos] = make_float2(__int_as_float(s * B), w);
    }

    // hop2 edges (~891K): int4 dst scan, filter dst >= OUT0 (~5.9% per edge)
    const int    E4 = E_ass >> 2;
    const int4*   a4 = (const int4*)a_dst;
    const int4*   s4p = (const int4*)a_src;
    const float4* w4p = (const float4*)a_w;
    for (int q = i; q < E4; q += nt) {
        int4 d4 = __ldg(&a4[q]);
        if (d4.x >= OUT0 || d4.y >= OUT0 || d4.z >= OUT0 || d4.w >= OUT0) {
            int4   s4 = __ldg(&s4p[q]);                // vectorized side loads
            float4 w4 = __ldg(&w4p[q]);
            int   dd[4] = {d4.x, d4.y, d4.z, d4.w};
            int   ss[4] = {s4.x, s4.y, s4.z, s4.w};
            float ww[4] = {w4.x, w4.y, w4.z, w4.w};
#pragma unroll
            for (int m = 0; m < 4; m++) {
                if (dd[m] >= OUT0) {
                    int d   = dd[m] - OUT0;
                    int s   = ss[m] - ASS0;
                    int pos = atomicAdd(&g_c2[d * CSTR], 1);
                    g_b2[d * CAP2 + pos] =
                        make_float2(__int_as_float(s * B), ww[m]);
                }
            }
        }
    }
    for (int e = (E4 << 2) + i; e < E_ass; e += nt) {  // tail (E_ass % 4)
        int d = a_dst[e];
        if (d >= OUT0) {
            int   dd = d - OUT0;
            int   s  = a_src[e] - ASS0;
            float w  = a_w[e];
            int pos  = atomicAdd(&g_c2[dd * CSTR], 1);
            g_b2[dd * CAP2 + pos] = make_float2(__int_as_float(s * B), w);
        }
    }
}

// ---------------------------------------------------------------- hop 1
// 2 nodes per 256-thread block; 8-wide predicated rounds (~2 rounds/node).
// Guarded loads: entries beyond n are stale from a prior replay — never read.
__global__ void __launch_bounds__(256) k_hop1() {
    __shared__ int sn[2];
    int g = threadIdx.x >> 7;              // 0..1
    int b = threadIdx.x & 127;
    int j = (blockIdx.x << 1) + g;
    if (b == 0) { sn[g] = g_c1[j * CSTR]; g_c1[j * CSTR] = 0; }  // consume+reset
    __syncthreads();
    int n = sn[g];
    const float2* bk = &g_b1[j * CAP1];
    float r = 0.f;
    for (int e = 0; e < n; e += 8) {
        float2 p[8];
#pragma unroll
        for (int k = 0; k < 8; k++)
            p[k] = (e + k < n) ? __ldg(&bk[e + k]) : make_float2(0.f, 0.f);
#pragma unroll
        for (int k = 0; k < 8; k++)
            r += p[k].y * g_xT[__float_as_int(p[k].x) + b];   // idx 0 when padded
    }
    g_acc1[j * B + b] = r;                             // coalesced
}

// ---------------------------------------------------------------- hop 2
// One output per block; 4 edge-groups x 128 batch threads (~51 edges each),
// 8-wide predicated rounds (~7 rounds), smem reduce of the 4 partials.
__global__ void __launch_bounds__(512) k_hop2(float* __restrict__ out) {
    __shared__ int   sc;
    __shared__ float part[3][B];
    int o = blockIdx.x;
    int g = threadIdx.x >> 7, b = threadIdx.x & 127;
    if (threadIdx.x == 0) { sc = g_c2[o * CSTR]; g_c2[o * CSTR] = 0; }
    __syncthreads();
    int n  = sc;
    int e0 = (n * g)       >> 2;
    int e1 = (n * (g + 1)) >> 2;
    const float2* bk = &g_b2[o * CAP2];
    float r = 0.f;
    for (int e = e0; e < e1; e += 8) {
        float2 p[8];
#pragma unroll
        for (int k = 0; k < 8; k++)
            p[k] = (e + k < e1) ? __ldg(&bk[e + k]) : make_float2(0.f, 0.f);
#pragma unroll
        for (int k = 0; k < 8; k++)
            r += p[k].y * g_acc1[__float_as_int(p[k].x) + b];
    }
    if (g > 0) part[g - 1][b] = r;
    __syncthreads();
    if (g == 0)
        out[b * OUT_F + o] = r + part[0][b] + part[1][b] + part[2][b];
}

// ---------------------------------------------------------------- launch
extern "C" void kernel_launch(void* const* d_in, const int* in_sizes, int n_in,
                              void* d_out, int out_size) {
    const float* x      = (const float*)d_in[0];
    const float* in_w   = (const float*)d_in[1];
    const float* a_w    = (const float*)d_in[2];
    const int*   in_src = (const int*)d_in[3];
    const int*   in_dst = (const int*)d_in[4];
    const int*   a_src  = (const int*)d_in[5];
    const int*   a_dst  = (const int*)d_in[6];
    int E_in  = in_sizes[1];
    int E_ass = in_sizes[2];
    float* out = (float*)d_out;

    k_build<<<1184, 256>>>(x, in_src, in_dst, in_w, E_in,
                           a_src, a_dst, a_w, E_ass);
    k_hop1 <<<N_ASS / 2, 256>>>();
    k_hop2 <<<OUT_F, 512>>>(out);
}

// round 11
// speedup vs baseline: 1.6178x; 1.4007x over previous
#include <cuda_runtime.h>

// Random_RNN two-hop — algebraic collapse: out = (W2*W1) * x^T.
// M = W2*W1 is 256x256 DENSE (64K floats). Build per-assoc edge buckets
// (in-edges keyed by dst j; out-edges keyed by SRC j), fold the per-j cross
// products into M with spread float atomics, then one tiny dense GEMM.
// Replaces ~54MB of hop gather traffic with ~0.3MB of M traffic.
//
// Established invariants kept: line-padded counters (L2 atomic units
// serialize per 128B line — the R8 14us fix), 3 plain launches (fusion w/
// grid barriers loses ~20us), counters consumed-and-reset for replay
// determinism, M re-zeroed in k1 every launch.

#define B      128
#define IN_F   256
#define N_ASS  4096
#define OUT_F  256
#define ASS0   256
#define OUT0   (IN_F + N_ASS)   // 4352
#define CAP1   40               // per-j in-degree  (E 12.8, sd 3.5)
#define CAP2   40               // per-j out-degree to outputs (E 12.8, sd 3.5)
#define XT_N   (IN_F * B)       // 32768
#define MSZ    (OUT_F * IN_F)   // 65536
#define CSTR   32               // counter stride: 32 ints = 128B = 1 L2 line

__device__ float2 g_b1[N_ASS * CAP1];   // in-edges of j:  {(float)s, w1}
__device__ float2 g_b2[N_ASS * CAP2];   // out-edges of j: {(float)o, w2}
__device__ int    g_c1[N_ASS * CSTR];   // one counter per L2 line
__device__ int    g_c2[N_ASS * CSTR];
__device__ float  g_xT[IN_F * B];       // x transposed [s][b]
__device__ float  g_M[MSZ];             // dense W2*W1, [o][s]

// ---------------------------------------------------------------- k1: build
// Proven R8 scan shape: 1184x256 grid-stride, int4 dst scan, conditional
// vectorized side loads, line-private counter atomics. Plus: zero M.
__global__ void __launch_bounds__(256, 8)
k_build(const float* __restrict__ x,
        const int* __restrict__ in_src, const int* __restrict__ in_dst,
        const float* __restrict__ in_w, int E_in,
        const int* __restrict__ a_src, const int* __restrict__ a_dst,
        const float* __restrict__ a_w, int E_ass) {
    const int i  = blockIdx.x * 256 + threadIdx.x;
    const int nt = gridDim.x * 256;

    if (i < MSZ) g_M[i] = 0.f;                         // nt > MSZ: one shot

    // x [B][IN_F] -> xT [IN_F][B]
    for (int idx = i; idx < XT_N; idx += nt) {
        int b = idx >> 8, s = idx & 255;               // IN_F == 256
        g_xT[s * B + b] = x[idx];
    }

    // hop1 edges (~52K): bucket by dst j
    for (int e = i; e < E_in; e += nt) {
        int   j = in_dst[e] - ASS0;
        int   s = in_src[e];
        float w = in_w[e];
        int pos = atomicAdd(&g_c1[j * CSTR], 1);
        g_b1[j * CAP1 + pos] = make_float2(__int_as_float(s), w);
    }

    // hop2 edges (~891K): int4 dst scan, filter dst >= OUT0; bucket by SRC j
    const int     E4  = E_ass >> 2;
    const int4*   a4  = (const int4*)a_dst;
    const int4*   s4p = (const int4*)a_src;
    const float4* w4p = (const float4*)a_w;
    for (int q = i; q < E4; q += nt) {
        int4 d4 = __ldg(&a4[q]);
        if (d4.x >= OUT0 || d4.y >= OUT0 || d4.z >= OUT0 || d4.w >= OUT0) {
            int4   s4 = __ldg(&s4p[q]);
            float4 w4 = __ldg(&w4p[q]);
            int   dd[4] = {d4.x, d4.y, d4.z, d4.w};
            int   ss[4] = {s4.x, s4.y, s4.z, s4.w};
            float ww[4] = {w4.x, w4.y, w4.z, w4.w};
#pragma unroll
            for (int m = 0; m < 4; m++) {
                if (dd[m] >= OUT0) {
                    int j   = ss[m] - ASS0;            // key by source assoc
                    int o   = dd[m] - OUT0;
                    int pos = atomicAdd(&g_c2[j * CSTR], 1);
                    g_b2[j * CAP2 + pos] =
                        make_float2(__int_as_float(o), ww[m]);
                }
            }
        }
    }
    for (int e = (E4 << 2) + i; e < E_ass; e += nt) {  // tail (E_ass % 4)
        int d = a_dst[e];
        if (d >= OUT0) {
            int   j = a_src[e] - ASS0;
            int   o = d - OUT0;
            float w = a_w[e];
            int pos = atomicAdd(&g_c2[j * CSTR], 1);
            g_b2[j * CAP2 + pos] = make_float2(__int_as_float(o), w);
        }
    }
}

// ---------------------------------------------------------------- k2: fold
// One warp per assoc j: lanes own in-edges (s,w1); loop over j's out-edges
// (o,w2) broadcast; M[o][s] += w1*w2. ~671K atomics spread over 2048 lines.
// Consumes + resets both counters (replay determinism).
__global__ void __launch_bounds__(256) k_fold() {
    int warp = threadIdx.x >> 5, lane = threadIdx.x & 31;
    int j = blockIdx.x * 8 + warp;                     // 512 blocks x 8 warps
    int n1 = __ldg(&g_c1[j * CSTR]);
    int n2 = __ldg(&g_c2[j * CSTR]);
    if (lane == 0) { g_c1[j * CSTR] = 0; g_c2[j * CSTR] = 0; }
    const float2* e1 = &g_b1[j * CAP1];
    const float2* e2 = &g_b2[j * CAP2];
    for (int t = lane; t < n1; t += 32) {              // n1 <= ~30
        float2 p1 = __ldg(&e1[t]);
        int   s  = __float_as_int(p1.x);
        float w1 = p1.y;
        for (int k = 0; k < n2; k++) {                 // broadcast reads
            float2 p2 = __ldg(&e2[k]);
            int   o  = __float_as_int(p2.x);
            atomicAdd(&g_M[o * IN_F + s], w1 * p2.y);
        }
    }
}

// ---------------------------------------------------------------- k3: gemm
// out[b][o] = sum_s M[o][s] * xT[s][b].  One output o per block; 4 s-groups
// x 128 batch threads, 8-wide rounds over the group's 64 s values, smem
// reduce. M row staged in smem; xT reads coalesced (L1-resident).
__global__ void __launch_bounds__(512) k_gemm(float* __restrict__ out) {
    __shared__ float sM[IN_F];
    __shared__ float part[3][B];
    int o = blockIdx.x;
    int g = threadIdx.x >> 7, b = threadIdx.x & 127;
    for (int s = threadIdx.x; s < IN_F; s += 512) sM[s] = g_M[o * IN_F + s];
    __syncthreads();
    float r = 0.f;
    int s0 = g * 64;
#pragma unroll
    for (int sr = 0; sr < 64; sr += 8) {               // 8 independent loads
        float v[8];
#pragma unroll
        for (int k = 0; k < 8; k++)
            v[k] = g_xT[(s0 + sr + k) * B + b];
#pragma unroll
        for (int k = 0; k < 8; k++)
            r += sM[s0 + sr + k] * v[k];
    }
    if (g > 0) part[g - 1][b] = r;
    __syncthreads();
    if (g == 0)
        out[b * OUT_F + o] = r + part[0][b] + part[1][b] + part[2][b];
}

// ---------------------------------------------------------------- launch
extern "C" void kernel_launch(void* const* d_in, const int* in_sizes, int n_in,
                              void* d_out, int out_size) {
    const float* x      = (const float*)d_in[0];
    const float* in_w   = (const float*)d_in[1];
    const float* a_w    = (const float*)d_in[2];
    const int*   in_src = (const int*)d_in[3];
    const int*   in_dst = (const int*)d_in[4];
    const int*   a_src  = (const int*)d_in[5];
    const int*   a_dst  = (const int*)d_in[6];
    int E_in  = in_sizes[1];
    int E_ass = in_sizes[2];
    float* out = (float*)d_out;

    k_build<<<1184, 256>>>(x, in_src, in_dst, in_w, E_in,
                           a_src, a_dst, a_w, E_ass);
    k_fold <<<N_ASS / 8, 256>>>();
    k_gemm <<<OUT_F, 512>>>(out);
}